// round 2
// baseline (speedup 1.0000x reference)
#include <cuda_runtime.h>
#include <cstdint>

// ============================================================================
// EdgeAttentionEmbedding — collapsed algebra + register-tiled GEMMs.
//
//   out[e] = softmax( c_e*(p[u]+p[v]) + ef[e]@Wb + bconst ),  c_e=(u==v)?1:0.5
//   p[n]   = node_features[n] @ M
//   M      = 0.5 * sum_h W1_h @ W3_h[:128]
//   Wb     = 0.5 * sum_h W3_h[128:192]
//   bconst = sum_h b1_h @ W3_h[:128] + 0.5 * sum_h b3_h
//
// GEMM tiling: block = 64 rows x 128 cols. Warp = 32 rows x 32 cols
// (4 row-lanes x 8 col-lanes), thread = 8 rows x 4 cols. A-operand staged
// transposed in smem (stride 68 floats: 16B-aligned + bank spread) so the
// inner loop is 3x LDS.128 + 16x FFMA2 per thread per k  ->  fma-pipe-bound.
// ============================================================================

#define MAXN 50176  // >= N (50000)
#define EPAD 68     // transposed-tile row stride in floats (16B aligned)

__device__ float g_M[128 * 128];
__device__ float g_Wb[64 * 128];
__device__ float g_bc[128];
__device__ float g_p[(size_t)MAXN * 128];

// ---------------------------------------------------------------------------
// Packed f32x2 helpers
// ---------------------------------------------------------------------------
__device__ __forceinline__ unsigned long long pack2(float a, float b) {
    unsigned long long r;
    asm("mov.b64 %0,{%1,%2};" : "=l"(r) : "r"(__float_as_uint(a)), "r"(__float_as_uint(b)));
    return r;
}
__device__ __forceinline__ unsigned long long dup2(float a) {
    unsigned long long r;
    unsigned int u = __float_as_uint(a);
    asm("mov.b64 %0,{%1,%1};" : "=l"(r) : "r"(u));
    return r;
}
__device__ __forceinline__ void unpack2(unsigned long long p, float& a, float& b) {
    unsigned int u0, u1;
    asm("mov.b64 {%0,%1},%2;" : "=r"(u0), "=r"(u1) : "l"(p));
    a = __uint_as_float(u0);
    b = __uint_as_float(u1);
}
__device__ __forceinline__ void fma2(unsigned long long& acc,
                                     unsigned long long a, unsigned long long b) {
    asm("fma.rn.f32x2 %0, %1, %2, %0;" : "+l"(acc) : "l"(a), "l"(b));
}

// ---------------------------------------------------------------------------
// Prep: fold per-head weights into M, Wb, bconst.
// ---------------------------------------------------------------------------
__global__ void prep_kernel(const float* __restrict__ W1,
                            const float* __restrict__ b1,
                            const float* __restrict__ W3,
                            const float* __restrict__ b3) {
    int j = threadIdx.x;
    int blk = blockIdx.x;
    if (blk < 128) {
        int i = blk;
        float acc = 0.f;
        #pragma unroll
        for (int h = 0; h < 2; h++) {
            const float* w1r = W1 + ((size_t)h * 128 + i) * 128;
            const float* w3  = W3 + (size_t)h * 192 * 128;
            #pragma unroll 16
            for (int k = 0; k < 128; k++)
                acc += w1r[k] * w3[k * 128 + j];
        }
        g_M[i * 128 + j] = 0.5f * acc;
    } else {
        #pragma unroll 8
        for (int r = 0; r < 64; r++) {
            float wv = 0.5f * (W3[(size_t)(128 + r) * 128 + j] +
                               W3[(size_t)192 * 128 + (size_t)(128 + r) * 128 + j]);
            g_Wb[r * 128 + j] = wv;
        }
        float a1 = 0.f, a2 = 0.f;
        #pragma unroll
        for (int h = 0; h < 2; h++) {
            const float* w3 = W3 + (size_t)h * 192 * 128;
            #pragma unroll 16
            for (int k = 0; k < 128; k++)
                a1 += b1[h * 128 + k] * w3[k * 128 + j];
            a2 += b3[h * 128 + j];
        }
        g_bc[j] = a1 + 0.5f * a2;
    }
}

// ---------------------------------------------------------------------------
// Node transform: p = node_features @ M.  Block = 64 nodes, K=128 in 4 chunks.
// ---------------------------------------------------------------------------
__global__ __launch_bounds__(256) void node_kernel(const float* __restrict__ x, int N) {
    __shared__ float sM[32 * 128];     // 16KB chunk of M
    __shared__ float sXt[32 * EPAD];   // transposed node tile

    int tid = threadIdx.x;
    int n_base = blockIdx.x * 64;
    int w = tid >> 5, lane = tid & 31;
    int we = w & 1, wc = w >> 1;
    int le = lane & 3, lc = lane >> 2;
    int c0 = wc * 32 + lc * 4;   // 4 output cols
    int nb = we * 32 + le * 8;   // 8 local nodes

    unsigned long long acc[8][2];
    #pragma unroll
    for (int i = 0; i < 8; i++) { acc[i][0] = 0ull; acc[i][1] = 0ull; }

    int ld_n  = tid >> 2;          // 0..63 local node for staging
    int ld_kq = (tid & 3) * 8;     // k offset within 32-chunk
    bool ld_ok = (n_base + ld_n) < N;

    #pragma unroll
    for (int chunk = 0; chunk < 4; chunk++) {
        __syncthreads();
        {   // stage M chunk
            const float4* src = (const float4*)(g_M + chunk * 32 * 128);
            float4* dst = (float4*)sM;
            #pragma unroll
            for (int i = tid; i < 1024; i += 256) dst[i] = src[i];
        }
        {   // stage node tile transposed
            float4 a = make_float4(0.f,0.f,0.f,0.f), b = a;
            if (ld_ok) {
                const float* src = x + (size_t)(n_base + ld_n) * 128 + chunk * 32 + ld_kq;
                a = *(const float4*)src;
                b = *(const float4*)(src + 4);
            }
            sXt[(ld_kq + 0) * EPAD + ld_n] = a.x;
            sXt[(ld_kq + 1) * EPAD + ld_n] = a.y;
            sXt[(ld_kq + 2) * EPAD + ld_n] = a.z;
            sXt[(ld_kq + 3) * EPAD + ld_n] = a.w;
            sXt[(ld_kq + 4) * EPAD + ld_n] = b.x;
            sXt[(ld_kq + 5) * EPAD + ld_n] = b.y;
            sXt[(ld_kq + 6) * EPAD + ld_n] = b.z;
            sXt[(ld_kq + 7) * EPAD + ld_n] = b.w;
        }
        __syncthreads();

        #pragma unroll 8
        for (int k = 0; k < 32; k++) {
            float4 wv = *(const float4*)(sM + (k << 7) + c0);
            unsigned long long mA = pack2(wv.x, wv.y);
            unsigned long long mB = pack2(wv.z, wv.w);
            float4 ea = *(const float4*)(sXt + k * EPAD + nb);
            float4 eb = *(const float4*)(sXt + k * EPAD + nb + 4);
            float ev[8] = {ea.x, ea.y, ea.z, ea.w, eb.x, eb.y, eb.z, eb.w};
            #pragma unroll
            for (int i = 0; i < 8; i++) {
                unsigned long long e2 = dup2(ev[i]);
                fma2(acc[i][0], e2, mA);
                fma2(acc[i][1], e2, mB);
            }
        }
    }

    #pragma unroll
    for (int i = 0; i < 8; i++) {
        int n = n_base + nb + i;
        if (n < N) {
            float v0, v1, v2, v3;
            unpack2(acc[i][0], v0, v1);
            unpack2(acc[i][1], v2, v3);
            *(float4*)(g_p + (size_t)n * 128 + c0) = make_float4(v0, v1, v2, v3);
        }
    }
}

// ---------------------------------------------------------------------------
// Fused edge kernel. Block = 64 edges. GEMM (ef@Wb) register-tiled, then
// logits staged in smem, warp-level softmax epilogue with p gathers.
// ---------------------------------------------------------------------------
__global__ __launch_bounds__(256) void edge_kernel(const float* __restrict__ ef,
                                                   const int* __restrict__ ei,
                                                   float* __restrict__ out, int E) {
    __shared__ float sBuf[64 * 128];   // 32KB: phase1 = sW(16K)+sEt(~8.7K), phase2 = logits
    __shared__ float sB[128];
    float* sW  = sBuf;          // 32*128
    float* sEt = sBuf + 4096;   // 32*EPAD
    float* sLog = sBuf;         // 64*128

    int tid = threadIdx.x;
    int e_base = blockIdx.x * 64;
    int w = tid >> 5, lane = tid & 31;
    int we = w & 1, wc = w >> 1;
    int le = lane & 3, lc = lane >> 2;
    int c0 = wc * 32 + lc * 4;
    int eb = we * 32 + le * 8;

    if (tid < 32)
        *(float4*)(sB + tid * 4) = *(const float4*)(g_bc + tid * 4);

    unsigned long long acc[8][2];
    #pragma unroll
    for (int i = 0; i < 8; i++) { acc[i][0] = 0ull; acc[i][1] = 0ull; }

    int ld_e  = tid >> 2;
    int ld_kq = (tid & 3) * 8;
    bool ld_ok = (e_base + ld_e) < E;

    #pragma unroll
    for (int half = 0; half < 2; half++) {
        __syncthreads();
        {   // stage Wb half
            const float4* src = (const float4*)(g_Wb + half * 32 * 128);
            float4* dst = (float4*)sW;
            #pragma unroll
            for (int i = tid; i < 1024; i += 256) dst[i] = src[i];
        }
        {   // stage ef tile transposed
            float4 a = make_float4(0.f,0.f,0.f,0.f), b = a;
            if (ld_ok) {
                const float* src = ef + (size_t)(e_base + ld_e) * 64 + half * 32 + ld_kq;
                a = *(const float4*)src;
                b = *(const float4*)(src + 4);
            }
            sEt[(ld_kq + 0) * EPAD + ld_e] = a.x;
            sEt[(ld_kq + 1) * EPAD + ld_e] = a.y;
            sEt[(ld_kq + 2) * EPAD + ld_e] = a.z;
            sEt[(ld_kq + 3) * EPAD + ld_e] = a.w;
            sEt[(ld_kq + 4) * EPAD + ld_e] = b.x;
            sEt[(ld_kq + 5) * EPAD + ld_e] = b.y;
            sEt[(ld_kq + 6) * EPAD + ld_e] = b.z;
            sEt[(ld_kq + 7) * EPAD + ld_e] = b.w;
        }
        __syncthreads();

        #pragma unroll 8
        for (int k = 0; k < 32; k++) {
            float4 wv = *(const float4*)(sW + (k << 7) + c0);
            unsigned long long mA = pack2(wv.x, wv.y);
            unsigned long long mB = pack2(wv.z, wv.w);
            float4 ea = *(const float4*)(sEt + k * EPAD + eb);
            float4 eb4 = *(const float4*)(sEt + k * EPAD + eb + 4);
            float ev[8] = {ea.x, ea.y, ea.z, ea.w, eb4.x, eb4.y, eb4.z, eb4.w};
            #pragma unroll
            for (int i = 0; i < 8; i++) {
                unsigned long long e2 = dup2(ev[i]);
                fma2(acc[i][0], e2, mA);
                fma2(acc[i][1], e2, mB);
            }
        }
    }

    __syncthreads();
    #pragma unroll
    for (int i = 0; i < 8; i++) {
        float v0, v1, v2, v3;
        unpack2(acc[i][0], v0, v1);
        unpack2(acc[i][1], v2, v3);
        *(float4*)(sLog + (eb + i) * 128 + c0) = make_float4(v0, v1, v2, v3);
    }
    __syncthreads();

    // Epilogue: warp w handles edges w*8 .. w*8+7 of this block's 64.
    int j = lane << 2;
    float4 bc = *(const float4*)(sB + j);
    #pragma unroll
    for (int t = 0; t < 8; t++) {
        int el = (w << 3) + t;
        int eg = e_base + el;
        bool ok = (eg < E);   // uniform across warp
        int u = 0, vtx = 0;
        if (ok) { u = ei[eg]; vtx = ei[E + eg]; }
        float cf = (u == vtx) ? 1.0f : 0.5f;
        float4 q = *(const float4*)(sLog + el * 128 + j);
        float4 pu = make_float4(0.f,0.f,0.f,0.f), pv = pu;
        if (ok) {
            pu = *(const float4*)(g_p + (size_t)u * 128 + j);
            pv = *(const float4*)(g_p + (size_t)vtx * 128 + j);
        }
        float v0 = fmaf(cf, pu.x + pv.x, q.x + bc.x);
        float v1 = fmaf(cf, pu.y + pv.y, q.y + bc.y);
        float v2 = fmaf(cf, pu.z + pv.z, q.z + bc.z);
        float v3 = fmaf(cf, pu.w + pv.w, q.w + bc.w);

        float mx = fmaxf(fmaxf(v0, v1), fmaxf(v2, v3));
        #pragma unroll
        for (int off = 16; off > 0; off >>= 1)
            mx = fmaxf(mx, __shfl_xor_sync(0xffffffffu, mx, off));
        v0 = __expf(v0 - mx);
        v1 = __expf(v1 - mx);
        v2 = __expf(v2 - mx);
        v3 = __expf(v3 - mx);
        float s = (v0 + v1) + (v2 + v3);
        #pragma unroll
        for (int off = 16; off > 0; off >>= 1)
            s += __shfl_xor_sync(0xffffffffu, s, off);
        float inv = __fdividef(1.0f, s);
        if (ok)
            *(float4*)(out + (size_t)eg * 128 + j) =
                make_float4(v0 * inv, v1 * inv, v2 * inv, v3 * inv);
    }
}

// ---------------------------------------------------------------------------
extern "C" void kernel_launch(void* const* d_in, const int* in_sizes, int n_in,
                              void* d_out, int out_size) {
    const float* node = (const float*)d_in[0];
    const float* ef   = (const float*)d_in[1];
    const int*   ei   = (const int*)d_in[2];
    const float* W1   = (const float*)d_in[3];
    const float* b1   = (const float*)d_in[4];
    const float* W3   = (const float*)d_in[7];
    const float* b3   = (const float*)d_in[8];

    int N = in_sizes[0] / 128;
    int E = in_sizes[1] / 64;
    float* out = (float*)d_out;

    prep_kernel<<<129, 128>>>(W1, b1, W3, b3);
    node_kernel<<<(N + 63) / 64, 256>>>(node, N);
    edge_kernel<<<(E + 63) / 64, 256>>>(ef, ei, out, E);
}